// round 13
// baseline (speedup 1.0000x reference)
#include <cuda_runtime.h>
#include <cuda_fp16.h>
#include <math.h>
#include <stdint.h>

#define LEN 2048
#define DIM 2048
#define NH 16
#define HD 128
#define SCALE 0.08838834764831845f   /* 1/sqrt(128) */
#define LOG2E 1.4426950408889634f
#define SOFT_OFF (4.0f * LOG2E)      /* fixed softmax offset, log2 domain */

// ---------------- scratch (allocation-free: __device__ globals) ----------------
__device__ __half g_qkv[(size_t)LEN * 3 * DIM];              // [L, 3*DIM] fp16

__device__ __half g_xh[(size_t)LEN * DIM];                   // x (fp16)
__device__ __half g_wqh[(size_t)3 * DIM * DIM];              // w_qkv (fp16)
__device__ __half g_wph[(size_t)DIM * DIM];                  // w_proj (fp16)
__device__ __half g_qh[(size_t)NH * LEN * HD];               // q*SCALE*log2e [H,L,D]
__device__ __half g_kh[(size_t)NH * LEN * HD];               // k (fp16) [H,L,D]
__device__ __half g_vth[(size_t)NH * HD * LEN];              // v^T (fp16) [H,D,L]
__device__ __half g_oh[(size_t)LEN * DIM];                   // O (fp16) [L, H*D]

// ---------------- helpers ----------------
static __device__ __forceinline__ unsigned cvta_smem(const void* p) {
    return (unsigned)__cvta_generic_to_shared(p);
}
static __device__ __forceinline__ unsigned pack2h(float x0, float x1) {
    __half2 h = __floats2half2_rn(x0, x1);
    return *reinterpret_cast<unsigned*>(&h);
}

#define LDSM4(r0, r1, r2, r3, addr)                                         \
    asm volatile("ldmatrix.sync.aligned.m8n8.x4.shared.b16 {%0,%1,%2,%3}, [%4];" \
                 : "=r"(r0), "=r"(r1), "=r"(r2), "=r"(r3) : "r"(addr))

#define MMA16816(d, a, b0_, b1_)                                            \
    asm volatile("mma.sync.aligned.m16n8k16.row.col.f32.f16.f16.f32 "      \
                 "{%0,%1,%2,%3},{%4,%5,%6,%7},{%8,%9},{%0,%1,%2,%3};"      \
                 : "+f"(d[0]), "+f"(d[1]), "+f"(d[2]), "+f"(d[3])           \
                 : "r"(a[0]), "r"(a[1]), "r"(a[2]), "r"(a[3]),              \
                   "r"(b0_), "r"(b1_))

#define CP_ASYNC16(dst, src) \
    asm volatile("cp.async.cg.shared.global [%0], [%1], 16;" \
                 :: "r"(dst), "l"(src) : "memory")
#define CP_COMMIT() asm volatile("cp.async.commit_group;" ::: "memory")
#define CP_WAIT1()  asm volatile("cp.async.wait_group 1;" ::: "memory")
#define CP_WAIT0()  asm volatile("cp.async.wait_group 0;" ::: "memory")

// ================= generic fp16 NT GEMM =================
template<int ROWS>
static __device__ __forceinline__ void load_tile(
    unsigned sbase, const __half* __restrict__ A,
    int ld, int kbase, int tid)
{
#pragma unroll
    for (int i = 0; i < ROWS / 32; ++i) {
        const int idx = tid + i * 256;
        const int row = idx >> 3;
        const int ch  = idx & 7;
        const unsigned dst = sbase + row * 128 + ((ch * 16) ^ ((row & 7) * 16));
        const __half* src = A + (long long)row * ld + kbase + ch * 8;
        CP_ASYNC16(dst, src);
    }
}

// C = alpha * A @ B^T (+bias). OUT = float or __half.
// CTA tile 128xBN, 256 threads, 8 warps 2(m)x4(n), warp tile 64xWN,
// BK=64, 3-stage cp.async, 1 sync/chunk, register-pipelined LDSM.
template<int BN, int WN, typename OUT>
__global__ __launch_bounds__(256, 1)
void gemm_nt_h2(const __half* __restrict__ Ah,
                const __half* __restrict__ Bh,
                OUT* __restrict__ C,
                int K, int lda, int ldb, int ldc,
                float alpha, const float* __restrict__ bias)
{
    constexpr int NT16  = WN / 16;
    constexpr int AT    = 128 * 64 * 2;
    constexpr int BT    = BN * 64 * 2;
    constexpr int STAGE = AT + BT;

    extern __shared__ char smem[];
    const unsigned smem_b = cvta_smem(smem);

    const int tid  = threadIdx.x;
    const int wid  = tid >> 5;
    const int lane = tid & 31;
    const int wm = (wid >> 2) * 64;
    const int wn = (wid & 3) * WN;
    const int m0 = blockIdx.y * 128;
    const int n0 = blockIdx.x * BN;

    const __half* pAh = Ah + (long long)m0 * lda;
    const __half* pBh = Bh + (long long)n0 * ldb;

    unsigned offA0[4], mskA[4];
    const unsigned cbA = ((lane >> 4) & 1) * 16;
#pragma unroll
    for (int mt = 0; mt < 4; ++mt) {
        const int r = wm + mt * 16 + (lane & 15);
        offA0[mt] = r * 128;
        mskA[mt]  = (r & 7) * 16;
    }
    unsigned offB0[NT16], mskB[NT16];
    const unsigned cbB = ((lane >> 3) & 1) * 16;
#pragma unroll
    for (int p = 0; p < NT16; ++p) {
        const int r = wn + p * 16 + (lane & 7) + ((lane >> 4) & 1) * 8;
        offB0[p] = r * 128;
        mskB[p]  = (r & 7) * 16;
    }

    float acc[4][2 * NT16][4];
#pragma unroll
    for (int i = 0; i < 4; ++i)
#pragma unroll
        for (int j = 0; j < 2 * NT16; ++j)
#pragma unroll
            for (int v = 0; v < 4; ++v) acc[i][j][v] = 0.0f;

    const int nch = K >> 6;

#pragma unroll
    for (int pc = 0; pc < 2; ++pc) {
        const unsigned sb = smem_b + pc * STAGE;
        const int kb = pc * 64;
        load_tile<128>(sb, pAh, lda, kb, tid);
        load_tile<BN>(sb + AT, pBh, ldb, kb, tid);
        CP_COMMIT();
    }

    for (int c = 0; c < nch; ++c) {
        if (c + 1 < nch) { CP_WAIT1(); } else { CP_WAIT0(); }
        __syncthreads();

        if (c + 2 < nch) {
            const unsigned sb2 = smem_b + ((c + 2) % 3) * STAGE;
            const int kb = (c + 2) * 64;
            load_tile<128>(sb2, pAh, lda, kb, tid);
            load_tile<BN>(sb2 + AT, pBh, ldb, kb, tid);
            CP_COMMIT();
        }

        const unsigned sb = smem_b + (c % 3) * STAGE;

        // A-fragment double buffer across ks
        unsigned ah[2][4][4];
#pragma unroll
        for (int mt = 0; mt < 4; ++mt) {
            const unsigned a0 = sb + offA0[mt] + (cbA ^ mskA[mt]);
            LDSM4(ah[0][mt][0], ah[0][mt][1], ah[0][mt][2], ah[0][mt][3], a0);
        }
#pragma unroll
        for (int ks = 0; ks < 4; ++ks) {
            const int cur = ks & 1;
            if (ks < 3) {
                const unsigned kb2 = (ks + 1) * 32;
#pragma unroll
                for (int mt = 0; mt < 4; ++mt) {
                    const unsigned a0 = sb + offA0[mt] + ((cbA + kb2) ^ mskA[mt]);
                    LDSM4(ah[cur ^ 1][mt][0], ah[cur ^ 1][mt][1],
                          ah[cur ^ 1][mt][2], ah[cur ^ 1][mt][3], a0);
                }
            }
            const unsigned kb = ks * 32;
            // B-fragment ping-pong across p
            unsigned bh[2][4];
            {
                const unsigned b0 = sb + AT + offB0[0] + ((cbB + kb) ^ mskB[0]);
                LDSM4(bh[0][0], bh[0][1], bh[0][2], bh[0][3], b0);
            }
#pragma unroll
            for (int p = 0; p < NT16; ++p) {
                if (p + 1 < NT16) {
                    const unsigned b0 = sb + AT + offB0[p + 1] + ((cbB + kb) ^ mskB[p + 1]);
                    LDSM4(bh[(p + 1) & 1][0], bh[(p + 1) & 1][1],
                          bh[(p + 1) & 1][2], bh[(p + 1) & 1][3], b0);
                }
                const unsigned* b = bh[p & 1];
#pragma unroll
                for (int mt = 0; mt < 4; ++mt) {
                    MMA16816(acc[mt][2 * p],     ah[cur][mt], b[0], b[1]);
                    MMA16816(acc[mt][2 * p + 1], ah[cur][mt], b[2], b[3]);
                }
            }
        }
    }

    const int g  = lane >> 2;
    const int tg = lane & 3;
#pragma unroll
    for (int mt = 0; mt < 4; ++mt) {
#pragma unroll
        for (int nt = 0; nt < 2 * NT16; ++nt) {
            const int r = m0 + wm + mt * 16 + g;
            const int c = n0 + wn + nt * 8 + tg * 2;
            float bx = 0.0f, by = 0.0f;
            if (bias) { bx = bias[c]; by = bias[c + 1]; }
            const float v00 = acc[mt][nt][0] * alpha + bx;
            const float v01 = acc[mt][nt][1] * alpha + by;
            const float v10 = acc[mt][nt][2] * alpha + bx;
            const float v11 = acc[mt][nt][3] * alpha + by;
            if (sizeof(OUT) == 4) {
                *reinterpret_cast<float2*>((float*)C + (long long)r * ldc + c) =
                    make_float2(v00, v01);
                *reinterpret_cast<float2*>((float*)C + (long long)(r + 8) * ldc + c) =
                    make_float2(v10, v11);
            } else {
                *reinterpret_cast<unsigned*>((__half*)C + (long long)r * ldc + c) =
                    pack2h(v00, v01);
                *reinterpret_cast<unsigned*>((__half*)C + (long long)(r + 8) * ldc + c) =
                    pack2h(v10, v11);
            }
        }
    }
}

#define GSMEM_SINGLE (3 * (16384 + 256 * 64 * 2))       /* 147456 */

// ================= flash attention =================
// grid (16 q-blocks, 16 heads), 256 threads (8 warps), each warp owns 16 q rows.
// smem: Q 32K | K 2x32K | V 2x32K = 160KB. Tiles 128x128 fp16,
// 256B pitch, swizzle: byte = row*256 + ((ch*16) ^ ((row&7)*16)), ch = col/8.
// No-max softmax (QKNorm bound), exp2 domain, P kept packed fp16,
// register-pipelined LDSM for aq/bk/bv.
#define FA_SMEM (160 * 1024)

static __device__ __forceinline__ void fa_load(
    unsigned dst, const __half* __restrict__ src, int ld, int tid)
{
#pragma unroll
    for (int i = 0; i < 8; ++i) {
        const int idx = tid + i * 256;
        const int row = idx >> 4;
        const int ch  = idx & 15;
        const unsigned d = dst + row * 256 + ((ch * 16) ^ ((row & 7) * 16));
        CP_ASYNC16(d, src + (long long)row * ld + ch * 8);
    }
}

__global__ __launch_bounds__(256, 1)
void flash_attn()
{
    extern __shared__ char smem[];
    const unsigned sb  = cvta_smem(smem);
    const unsigned sQ  = sb;
    const unsigned sK  = sb + 32768;
    const unsigned sV  = sb + 98304;

    const int tid  = threadIdx.x;
    const int wid  = tid >> 5;
    const int lane = tid & 31;
    const int qb = blockIdx.x;
    const int h  = blockIdx.y;

    const __half* Qh = g_qh + ((size_t)h * LEN + qb * 128) * HD;
    const __half* Kh = g_kh + (size_t)h * LEN * HD;
    const __half* Vt = g_vth + (size_t)h * HD * LEN;

    fa_load(sQ, Qh, HD, tid);
    fa_load(sK, Kh, HD, tid);
    fa_load(sV, Vt, LEN, tid);
    CP_COMMIT();
    fa_load(sK + 32768, Kh + 128 * HD, HD, tid);
    fa_load(sV + 32768, Vt + 128, LEN, tid);
    CP_COMMIT();

    const int q0 = wid * 16;
    const unsigned rowA256 = (q0 + (lane & 15)) * 256;
    const unsigned mskA    = (lane & 7) * 16;
    const unsigned caA     = ((lane >> 4) & 1) * 16;
    const int rB0          = (lane & 7) + ((lane >> 4) & 1) * 8;
    const unsigned rowB256 = rB0 * 256;
    const unsigned mskB    = (rB0 & 7) * 16;
    const unsigned cbB     = ((lane >> 3) & 1) * 16;

    float o[16][4];
#pragma unroll
    for (int i = 0; i < 16; ++i)
#pragma unroll
        for (int v = 0; v < 4; ++v) o[i][v] = 0.0f;
    float l0 = 0.0f, l1 = 0.0f;

    const int NB = LEN / 128;
    for (int j = 0; j < NB; ++j) {
        if (j + 1 < NB) { CP_WAIT1(); } else { CP_WAIT0(); }
        __syncthreads();

        const unsigned kbuf = sK + (j & 1) * 32768;
        const unsigned vbuf = sV + (j & 1) * 32768;

        // ---- S = Q @ K^T + (-offset), log2 domain ----
        float s[16][4];
#pragma unroll
        for (int i = 0; i < 16; ++i)
#pragma unroll
            for (int v = 0; v < 4; ++v) s[i][v] = -SOFT_OFF;

        unsigned aq[2][4];
        LDSM4(aq[0][0], aq[0][1], aq[0][2], aq[0][3],
              sQ + rowA256 + (caA ^ mskA));
#pragma unroll
        for (int kd = 0; kd < 8; ++kd) {
            const int cur = kd & 1;
            if (kd < 7) {
                const unsigned ca = ((kd + 1) * 32 + caA) ^ mskA;
                LDSM4(aq[cur ^ 1][0], aq[cur ^ 1][1],
                      aq[cur ^ 1][2], aq[cur ^ 1][3], sQ + rowA256 + ca);
            }
            const unsigned cb = (kd * 32 + cbB) ^ mskB;
            unsigned bk[2][4];
            LDSM4(bk[0][0], bk[0][1], bk[0][2], bk[0][3], kbuf + rowB256 + cb);
#pragma unroll
            for (int p = 0; p < 8; ++p) {
                if (p < 7) {
                    LDSM4(bk[(p + 1) & 1][0], bk[(p + 1) & 1][1],
                          bk[(p + 1) & 1][2], bk[(p + 1) & 1][3],
                          kbuf + rowB256 + (p + 1) * 4096 + cb);
                }
                const unsigned* b = bk[p & 1];
                MMA16816(s[2 * p],     aq[cur], b[0], b[1]);
                MMA16816(s[2 * p + 1], aq[cur], b[2], b[3]);
            }
        }

        // ---- exp2 + row-sum + pack to fp16 P in one pass ----
        unsigned P[8][4];
#pragma unroll
        for (int kt = 0; kt < 8; ++kt) {
            const float e00 = exp2f(s[2 * kt][0]);
            const float e01 = exp2f(s[2 * kt][1]);
            const float e02 = exp2f(s[2 * kt][2]);
            const float e03 = exp2f(s[2 * kt][3]);
            const float e10 = exp2f(s[2 * kt + 1][0]);
            const float e11 = exp2f(s[2 * kt + 1][1]);
            const float e12 = exp2f(s[2 * kt + 1][2]);
            const float e13 = exp2f(s[2 * kt + 1][3]);
            l0 += e00; l0 += e01; l1 += e02; l1 += e03;
            l0 += e10; l0 += e11; l1 += e12; l1 += e13;
            P[kt][0] = pack2h(e00, e01);
            P[kt][1] = pack2h(e02, e03);
            P[kt][2] = pack2h(e10, e11);
            P[kt][3] = pack2h(e12, e13);
        }

        // ---- O += P @ V^T ----
#pragma unroll
        for (int kt = 0; kt < 8; ++kt) {
            const unsigned cb = (kt * 32 + cbB) ^ mskB;
            unsigned bv[2][4];
            LDSM4(bv[0][0], bv[0][1], bv[0][2], bv[0][3], vbuf + rowB256 + cb);
#pragma unroll
            for (int dt = 0; dt < 8; ++dt) {
                if (dt < 7) {
                    LDSM4(bv[(dt + 1) & 1][0], bv[(dt + 1) & 1][1],
                          bv[(dt + 1) & 1][2], bv[(dt + 1) & 1][3],
                          vbuf + rowB256 + (dt + 1) * 4096 + cb);
                }
                const unsigned* b = bv[dt & 1];
                MMA16816(o[2 * dt],     P[kt], b[0], b[1]);
                MMA16816(o[2 * dt + 1], P[kt], b[2], b[3]);
            }
        }

        __syncthreads();
        if (j + 2 < NB) {
            const unsigned kb2 = sK + (j & 1) * 32768;
            const unsigned vb2 = sV + (j & 1) * 32768;
            fa_load(kb2, Kh + (long long)(j + 2) * 128 * HD, HD, tid);
            fa_load(vb2, Vt + (j + 2) * 128, LEN, tid);
            CP_COMMIT();
        }
    }

    // ---- epilogue: normalize, store fp16 O [L, H*D] ----
    l0 += __shfl_xor_sync(0xffffffffu, l0, 1);
    l0 += __shfl_xor_sync(0xffffffffu, l0, 2);
    l1 += __shfl_xor_sync(0xffffffffu, l1, 1);
    l1 += __shfl_xor_sync(0xffffffffu, l1, 2);
    const float inv0 = 1.0f / l0;
    const float inv1 = 1.0f / l1;

    const int r0g = qb * 128 + q0 + (lane >> 2);
#pragma unroll
    for (int nt = 0; nt < 16; ++nt) {
        const int d = nt * 8 + (lane & 3) * 2;
        const size_t i0 = (size_t)r0g * DIM + h * HD + d;
        const size_t i1 = i0 + (size_t)8 * DIM;
        *reinterpret_cast<unsigned*>(&g_oh[i0]) =
            pack2h(o[nt][0] * inv0, o[nt][1] * inv0);
        *reinterpret_cast<unsigned*>(&g_oh[i1]) =
            pack2h(o[nt][2] * inv1, o[nt][3] * inv1);
    }
}

// ---------------- round x / w_qkv / w_proj to fp16 ----------------
#define SEG_X  (LEN * DIM / 4)
#define SEG_WQ (3 * DIM * DIM / 4)
#define SEG_WP (DIM * DIM / 4)
__global__ void split_inputs(const float* __restrict__ x,
                             const float* __restrict__ wq,
                             const float* __restrict__ wp)
{
    const int i = blockIdx.x * blockDim.x + threadIdx.x;
    if (i < SEG_X) {
        float4 v = reinterpret_cast<const float4*>(x)[i];
        reinterpret_cast<uint2*>(g_xh)[i] =
            make_uint2(pack2h(v.x, v.y), pack2h(v.z, v.w));
    } else if (i < SEG_X + SEG_WQ) {
        const int j = i - SEG_X;
        float4 v = reinterpret_cast<const float4*>(wq)[j];
        reinterpret_cast<uint2*>(g_wqh)[j] =
            make_uint2(pack2h(v.x, v.y), pack2h(v.z, v.w));
    } else if (i < SEG_X + SEG_WQ + SEG_WP) {
        const int j = i - SEG_X - SEG_WQ;
        float4 v = reinterpret_cast<const float4*>(wp)[j];
        reinterpret_cast<uint2*>(g_wph)[j] =
            make_uint2(pack2h(v.x, v.y), pack2h(v.z, v.w));
    }
}

// ---------------- QK RMSNorm + RoPE + V transpose (fp16 qkv input) ------------
__global__ void qknorm_rope(const float* __restrict__ pe,
                            const float* __restrict__ qs,
                            const float* __restrict__ ks)
{
    const int l = blockIdx.x;
    const int h = blockIdx.y;
    const int d = threadIdx.x;

    const __half* base = g_qkv + (size_t)l * (3 * DIM) + h * HD;
    float q = __half2float(base[d]);
    float k = __half2float(base[DIM + d]);
    float v = __half2float(base[2 * DIM + d]);

    float sq = q * q, sk = k * k;
#pragma unroll
    for (int o = 16; o; o >>= 1) {
        sq += __shfl_xor_sync(0xffffffffu, sq, o);
        sk += __shfl_xor_sync(0xffffffffu, sk, o);
    }
    __shared__ float rq[4], rk[4];
    const int w = d >> 5;
    if ((d & 31) == 0) { rq[w] = sq; rk[w] = sk; }
    __syncthreads();
    sq = rq[0] + rq[1] + rq[2] + rq[3];
    sk = rk[0] + rk[1] + rk[2] + rk[3];

    const float rrq = rsqrtf(sq * (1.0f / HD) + 1e-6f);
    const float rrk = rsqrtf(sk * (1.0f / HD) + 1e-6f);
    float qn = q * rrq * qs[d];
    float kn = k * rrk * ks[d];

    const float qp = __shfl_xor_sync(0xffffffffu, qn, 1);
    const float kp = __shfl_xor_sync(0xffffffffu, kn, 1);
    const int j = d >> 1, a = d & 1;
    const float* p = pe + (size_t)l * (HD / 2) * 4 + j * 4 + a * 2;
    const float q0 = a ? qp : qn, q1 = a ? qn : qp;
    const float k0 = a ? kp : kn, k1 = a ? kn : kp;
    const float qr = (p[0] * q0 + p[1] * q1) * (SCALE * LOG2E);
    const float kr = p[0] * k0 + p[1] * k1;

    const size_t idx = ((size_t)h * LEN + l) * HD + d;
    g_qh[idx] = __float2half_rn(qr);
    g_kh[idx] = __float2half_rn(kr);
    g_vth[((size_t)h * HD + d) * LEN + l] = __float2half_rn(v);
}

// ---------------- launch ----------------
extern "C" void kernel_launch(void* const* d_in, const int* in_sizes, int n_in,
                              void* d_out, int out_size)
{
    const float* x      = (const float*)d_in[0];
    const float* pe     = (const float*)d_in[1];
    const float* w_qkv  = (const float*)d_in[2];
    const float* q_sc   = (const float*)d_in[3];
    const float* k_sc   = (const float*)d_in[4];
    const float* w_proj = (const float*)d_in[5];
    const float* b_proj = (const float*)d_in[6];
    float* out = (float*)d_out;

    __half *p_qkv, *p_xh, *p_wqh, *p_wph, *p_oh;
    cudaGetSymbolAddress((void**)&p_qkv, g_qkv);
    cudaGetSymbolAddress((void**)&p_xh,  g_xh);
    cudaGetSymbolAddress((void**)&p_wqh, g_wqh);
    cudaGetSymbolAddress((void**)&p_wph, g_wph);
    cudaGetSymbolAddress((void**)&p_oh,  g_oh);

    cudaFuncSetAttribute((const void*)gemm_nt_h2<256, 64, __half>,
                         cudaFuncAttributeMaxDynamicSharedMemorySize, GSMEM_SINGLE);
    cudaFuncSetAttribute((const void*)gemm_nt_h2<256, 64, float>,
                         cudaFuncAttributeMaxDynamicSharedMemorySize, GSMEM_SINGLE);
    cudaFuncSetAttribute((const void*)flash_attn,
                         cudaFuncAttributeMaxDynamicSharedMemorySize, FA_SMEM);

    // 0) round x, weights to fp16
    {
        const int total = SEG_X + SEG_WQ + SEG_WP;
        split_inputs<<<(total + 255) / 256, 256>>>(x, w_qkv, w_proj);
    }

    // 1) QKV = x @ w_qkv^T : [2048, 6144] fp16 output
    gemm_nt_h2<256, 64, __half><<<dim3(6144 / 256, 2048 / 128, 1), 256, GSMEM_SINGLE>>>(
        p_xh, p_wqh, p_qkv, 2048, 2048, 2048, 6144, 1.0f, nullptr);

    // 2) QK RMSNorm + RoPE + V transpose (SCALE*log2e folded into Q)
    qknorm_rope<<<dim3(LEN, NH), HD>>>(pe, q_sc, k_sc);

    // 3) fused attention (no-max softmax, exp2, pipelined LDSM)
    flash_attn<<<dim3(LEN / 128, NH), 256, FA_SMEM>>>();

    // 4) out = O @ w_proj^T + b_proj : [2048, 2048] fp32
    gemm_nt_h2<256, 64, float><<<dim3(2048 / 256, 2048 / 128, 1), 256, GSMEM_SINGLE>>>(
        p_oh, p_wph, out, 2048, 2048, 2048, 2048, 1.0f, b_proj);
}

// round 14
// speedup vs baseline: 1.0198x; 1.0198x over previous
#include <cuda_runtime.h>
#include <cuda_fp16.h>
#include <math.h>
#include <stdint.h>

#define LEN 2048
#define DIM 2048
#define NH 16
#define HD 128
#define SCALE 0.08838834764831845f   /* 1/sqrt(128) */
#define LOG2E 1.4426950408889634f
#define SOFT_OFF (4.0f * LOG2E)      /* fixed softmax offset, log2 domain */

// ---------------- scratch (allocation-free: __device__ globals) ----------------
__device__ __half g_qkv[(size_t)LEN * 3 * DIM];              // [L, 3*DIM] fp16

__device__ __half g_xh[(size_t)LEN * DIM];                   // x (fp16)
__device__ __half g_wqh[(size_t)3 * DIM * DIM];              // w_qkv (fp16)
__device__ __half g_wph[(size_t)DIM * DIM];                  // w_proj (fp16)
__device__ __half g_qh[(size_t)NH * LEN * HD];               // q*SCALE*log2e [H,L,D]
__device__ __half g_kh[(size_t)NH * LEN * HD];               // k (fp16) [H,L,D]
__device__ __half g_vth[(size_t)NH * HD * LEN];              // v^T (fp16) [H,D,L]
__device__ __half g_oh[(size_t)LEN * DIM];                   // O (fp16) [L, H*D]

// ---------------- helpers ----------------
static __device__ __forceinline__ unsigned cvta_smem(const void* p) {
    return (unsigned)__cvta_generic_to_shared(p);
}
static __device__ __forceinline__ unsigned pack2h(float x0, float x1) {
    __half2 h = __floats2half2_rn(x0, x1);
    return *reinterpret_cast<unsigned*>(&h);
}

#define LDSM4(r0, r1, r2, r3, addr)                                         \
    asm volatile("ldmatrix.sync.aligned.m8n8.x4.shared.b16 {%0,%1,%2,%3}, [%4];" \
                 : "=r"(r0), "=r"(r1), "=r"(r2), "=r"(r3) : "r"(addr))

#define MMA16816(d, a, b0_, b1_)                                            \
    asm volatile("mma.sync.aligned.m16n8k16.row.col.f32.f16.f16.f32 "      \
                 "{%0,%1,%2,%3},{%4,%5,%6,%7},{%8,%9},{%0,%1,%2,%3};"      \
                 : "+f"(d[0]), "+f"(d[1]), "+f"(d[2]), "+f"(d[3])           \
                 : "r"(a[0]), "r"(a[1]), "r"(a[2]), "r"(a[3]),              \
                   "r"(b0_), "r"(b1_))

#define CP_ASYNC16(dst, src) \
    asm volatile("cp.async.cg.shared.global [%0], [%1], 16;" \
                 :: "r"(dst), "l"(src) : "memory")
#define CP_COMMIT() asm volatile("cp.async.commit_group;" ::: "memory")
#define CP_WAIT1()  asm volatile("cp.async.wait_group 1;" ::: "memory")
#define CP_WAIT0()  asm volatile("cp.async.wait_group 0;" ::: "memory")

// ================= generic fp16 NT GEMM (round-12 config) =================
template<int ROWS>
static __device__ __forceinline__ void load_tile(
    unsigned sbase, const __half* __restrict__ A,
    int ld, int kbase, int tid)
{
#pragma unroll
    for (int i = 0; i < ROWS / 32; ++i) {
        const int idx = tid + i * 256;
        const int row = idx >> 3;
        const int ch  = idx & 7;
        const unsigned dst = sbase + row * 128 + ((ch * 16) ^ ((row & 7) * 16));
        const __half* src = A + (long long)row * ld + kbase + ch * 8;
        CP_ASYNC16(dst, src);
    }
}

// C = alpha * A @ B^T (+bias). OUT = float or __half.
// CTA tile 128xBN, 256 threads, 8 warps 2(m)x4(n), warp tile 64xWN,
// BK=64, 3-stage cp.async, 1 sync/chunk.
template<int BN, int WN, typename OUT>
__global__ __launch_bounds__(256, 1)
void gemm_nt_h2(const __half* __restrict__ Ah,
                const __half* __restrict__ Bh,
                OUT* __restrict__ C,
                int K, int lda, int ldb, int ldc,
                float alpha, const float* __restrict__ bias)
{
    constexpr int NT16  = WN / 16;
    constexpr int AT    = 128 * 64 * 2;
    constexpr int BT    = BN * 64 * 2;
    constexpr int STAGE = AT + BT;

    extern __shared__ char smem[];
    const unsigned smem_b = cvta_smem(smem);

    const int tid  = threadIdx.x;
    const int wid  = tid >> 5;
    const int lane = tid & 31;
    const int wm = (wid >> 2) * 64;
    const int wn = (wid & 3) * WN;
    const int m0 = blockIdx.y * 128;
    const int n0 = blockIdx.x * BN;

    const __half* pAh = Ah + (long long)m0 * lda;
    const __half* pBh = Bh + (long long)n0 * ldb;

    unsigned offA0[4], mskA[4];
    const unsigned cbA = ((lane >> 4) & 1) * 16;
#pragma unroll
    for (int mt = 0; mt < 4; ++mt) {
        const int r = wm + mt * 16 + (lane & 15);
        offA0[mt] = r * 128;
        mskA[mt]  = (r & 7) * 16;
    }
    unsigned offB0[NT16], mskB[NT16];
    const unsigned cbB = ((lane >> 3) & 1) * 16;
#pragma unroll
    for (int p = 0; p < NT16; ++p) {
        const int r = wn + p * 16 + (lane & 7) + ((lane >> 4) & 1) * 8;
        offB0[p] = r * 128;
        mskB[p]  = (r & 7) * 16;
    }

    float acc[4][2 * NT16][4];
#pragma unroll
    for (int i = 0; i < 4; ++i)
#pragma unroll
        for (int j = 0; j < 2 * NT16; ++j)
#pragma unroll
            for (int v = 0; v < 4; ++v) acc[i][j][v] = 0.0f;

    const int nch = K >> 6;

#pragma unroll
    for (int pc = 0; pc < 2; ++pc) {
        const unsigned sb = smem_b + pc * STAGE;
        const int kb = pc * 64;
        load_tile<128>(sb, pAh, lda, kb, tid);
        load_tile<BN>(sb + AT, pBh, ldb, kb, tid);
        CP_COMMIT();
    }

    for (int c = 0; c < nch; ++c) {
        if (c + 1 < nch) { CP_WAIT1(); } else { CP_WAIT0(); }
        __syncthreads();

        if (c + 2 < nch) {
            const unsigned sb2 = smem_b + ((c + 2) % 3) * STAGE;
            const int kb = (c + 2) * 64;
            load_tile<128>(sb2, pAh, lda, kb, tid);
            load_tile<BN>(sb2 + AT, pBh, ldb, kb, tid);
            CP_COMMIT();
        }

        const unsigned sb = smem_b + (c % 3) * STAGE;
#pragma unroll
        for (int ks = 0; ks < 4; ++ks) {
            const unsigned kb = ks * 32;
            unsigned ah[4][4];
#pragma unroll
            for (int mt = 0; mt < 4; ++mt) {
                const unsigned a0 = sb + offA0[mt] + ((cbA + kb) ^ mskA[mt]);
                LDSM4(ah[mt][0], ah[mt][1], ah[mt][2], ah[mt][3], a0);
            }
#pragma unroll
            for (int p = 0; p < NT16; ++p) {
                const unsigned b0 = sb + AT + offB0[p] + ((cbB + kb) ^ mskB[p]);
                unsigned bh[4];
                LDSM4(bh[0], bh[1], bh[2], bh[3], b0);
#pragma unroll
                for (int mt = 0; mt < 4; ++mt) {
                    MMA16816(acc[mt][2 * p],     ah[mt], bh[0], bh[1]);
                    MMA16816(acc[mt][2 * p + 1], ah[mt], bh[2], bh[3]);
                }
            }
        }
    }

    const int g  = lane >> 2;
    const int tg = lane & 3;
#pragma unroll
    for (int mt = 0; mt < 4; ++mt) {
#pragma unroll
        for (int nt = 0; nt < 2 * NT16; ++nt) {
            const int r = m0 + wm + mt * 16 + g;
            const int c = n0 + wn + nt * 8 + tg * 2;
            float bx = 0.0f, by = 0.0f;
            if (bias) { bx = bias[c]; by = bias[c + 1]; }
            const float v00 = acc[mt][nt][0] * alpha + bx;
            const float v01 = acc[mt][nt][1] * alpha + by;
            const float v10 = acc[mt][nt][2] * alpha + bx;
            const float v11 = acc[mt][nt][3] * alpha + by;
            if (sizeof(OUT) == 4) {
                *reinterpret_cast<float2*>((float*)C + (long long)r * ldc + c) =
                    make_float2(v00, v01);
                *reinterpret_cast<float2*>((float*)C + (long long)(r + 8) * ldc + c) =
                    make_float2(v10, v11);
            } else {
                *reinterpret_cast<unsigned*>((__half*)C + (long long)r * ldc + c) =
                    pack2h(v00, v01);
                *reinterpret_cast<unsigned*>((__half*)C + (long long)(r + 8) * ldc + c) =
                    pack2h(v10, v11);
            }
        }
    }
}

#define GSMEM_SINGLE (3 * (16384 + 256 * 64 * 2))       /* 147456 */

// ================= flash attention =================
// grid (16 q-blocks, 16 heads), 256 threads (8 warps), each warp owns 16 q rows.
// smem: Q 32K | K 3x32K | V 3x32K = 224KB. Tiles 128x128 fp16, 256B pitch,
// swizzle: byte = row*256 + ((ch*16) ^ ((row&7)*16)), ch = col/8.
// No-max softmax (QKNorm bound), exp2 domain, persistent Q fragments,
// 3-stage K/V pipeline with ONE barrier per iteration, exp fused into PV.
#define FA_SMEM (224 * 1024)

static __device__ __forceinline__ void fa_load(
    unsigned dst, const __half* __restrict__ src, int ld, int tid)
{
#pragma unroll
    for (int i = 0; i < 8; ++i) {
        const int idx = tid + i * 256;
        const int row = idx >> 4;
        const int ch  = idx & 15;
        const unsigned d = dst + row * 256 + ((ch * 16) ^ ((row & 7) * 16));
        CP_ASYNC16(d, src + (long long)row * ld + ch * 8);
    }
}

__global__ __launch_bounds__(256, 1)
void flash_attn()
{
    extern __shared__ char smem[];
    const unsigned sb  = cvta_smem(smem);
    const unsigned sQ  = sb;
    const unsigned sK  = sb + 32768;     // + s*32768, s in 0..2
    const unsigned sV  = sb + 131072;    // + s*32768, s in 0..2

    const int tid  = threadIdx.x;
    const int wid  = tid >> 5;
    const int lane = tid & 31;
    const int qb = blockIdx.x;
    const int h  = blockIdx.y;

    const __half* Qh = g_qh + ((size_t)h * LEN + qb * 128) * HD;
    const __half* Kh = g_kh + (size_t)h * LEN * HD;
    const __half* Vt = g_vth + (size_t)h * HD * LEN;

    // prologue: G0 = {Q, K0, V0}, G1 = {K1, V1}
    fa_load(sQ, Qh, HD, tid);
    fa_load(sK, Kh, HD, tid);
    fa_load(sV, Vt, LEN, tid);
    CP_COMMIT();
    fa_load(sK + 32768, Kh + 128 * HD, HD, tid);
    fa_load(sV + 32768, Vt + 128, LEN, tid);
    CP_COMMIT();

    const int q0 = wid * 16;
    const unsigned rowA256 = (q0 + (lane & 15)) * 256;
    const unsigned mskA    = (lane & 7) * 16;
    const unsigned caA     = ((lane >> 4) & 1) * 16;
    const int rB0          = (lane & 7) + ((lane >> 4) & 1) * 8;
    const unsigned rowB256 = rB0 * 256;
    const unsigned mskB    = (rB0 & 7) * 16;
    const unsigned cbB     = ((lane >> 3) & 1) * 16;

    // wait for G0 (Q ready), then load persistent Q fragments
    CP_WAIT1();
    __syncthreads();
    unsigned aq[8][4];
#pragma unroll
    for (int kd = 0; kd < 8; ++kd) {
        const unsigned ca = (kd * 32 + caA) ^ mskA;
        LDSM4(aq[kd][0], aq[kd][1], aq[kd][2], aq[kd][3], sQ + rowA256 + ca);
    }

    float o[16][4];
#pragma unroll
    for (int i = 0; i < 16; ++i)
#pragma unroll
        for (int v = 0; v < 4; ++v) o[i][v] = 0.0f;
    float l0 = 0.0f, l1 = 0.0f;

    const int NB = LEN / 128;
    int stage = 0;
    for (int j = 0; j < NB; ++j) {
        if (j > 0) {
            if (j + 1 < NB) { CP_WAIT1(); } else { CP_WAIT0(); }
            __syncthreads();
        }

        // prefetch j+2 into buffer (j+2)%3 (read last at j-1; safe after sync)
        if (j + 2 < NB) {
            const int s2 = (stage + 2 >= 3) ? stage - 1 : stage + 2;
            fa_load(sK + s2 * 32768, Kh + (long long)(j + 2) * 128 * HD, HD, tid);
            fa_load(sV + s2 * 32768, Vt + (j + 2) * 128, LEN, tid);
            CP_COMMIT();
        }

        const unsigned kbuf = sK + stage * 32768;
        const unsigned vbuf = sV + stage * 32768;
        stage = (stage + 1 == 3) ? 0 : stage + 1;

        // ---- S = Q @ K^T + (-offset), log2 domain ----
        float s[16][4];
#pragma unroll
        for (int i = 0; i < 16; ++i)
#pragma unroll
            for (int v = 0; v < 4; ++v) s[i][v] = -SOFT_OFF;

#pragma unroll
        for (int kd = 0; kd < 8; ++kd) {
            const unsigned cb = (kd * 32 + cbB) ^ mskB;
#pragma unroll
            for (int p = 0; p < 8; ++p) {
                unsigned bk[4];
                LDSM4(bk[0], bk[1], bk[2], bk[3], kbuf + rowB256 + p * 4096 + cb);
                MMA16816(s[2 * p],     aq[kd], bk[0], bk[1]);
                MMA16816(s[2 * p + 1], aq[kd], bk[2], bk[3]);
            }
        }

        // ---- fused exp2 + pack + PV per key-16 tile ----
#pragma unroll
        for (int kt = 0; kt < 8; ++kt) {
            const float e00 = exp2f(s[2 * kt][0]);
            const float e01 = exp2f(s[2 * kt][1]);
            const float e02 = exp2f(s[2 * kt][2]);
            const float e03 = exp2f(s[2 * kt][3]);
            const float e10 = exp2f(s[2 * kt + 1][0]);
            const float e11 = exp2f(s[2 * kt + 1][1]);
            const float e12 = exp2f(s[2 * kt + 1][2]);
            const float e13 = exp2f(s[2 * kt + 1][3]);
            l0 += e00; l0 += e01; l1 += e02; l1 += e03;
            l0 += e10; l0 += e11; l1 += e12; l1 += e13;
            unsigned ph[4];
            ph[0] = pack2h(e00, e01);
            ph[1] = pack2h(e02, e03);
            ph[2] = pack2h(e10, e11);
            ph[3] = pack2h(e12, e13);

            const unsigned cb = (kt * 32 + cbB) ^ mskB;
#pragma unroll
            for (int dt = 0; dt < 8; ++dt) {
                unsigned bv[4];
                LDSM4(bv[0], bv[1], bv[2], bv[3], vbuf + rowB256 + dt * 4096 + cb);
                MMA16816(o[2 * dt],     ph, bv[0], bv[1]);
                MMA16816(o[2 * dt + 1], ph, bv[2], bv[3]);
            }
        }
    }

    // ---- epilogue: normalize, store fp16 O [L, H*D] ----
    l0 += __shfl_xor_sync(0xffffffffu, l0, 1);
    l0 += __shfl_xor_sync(0xffffffffu, l0, 2);
    l1 += __shfl_xor_sync(0xffffffffu, l1, 1);
    l1 += __shfl_xor_sync(0xffffffffu, l1, 2);
    const float inv0 = 1.0f / l0;
    const float inv1 = 1.0f / l1;

    const int r0g = qb * 128 + q0 + (lane >> 2);
#pragma unroll
    for (int nt = 0; nt < 16; ++nt) {
        const int d = nt * 8 + (lane & 3) * 2;
        const size_t i0 = (size_t)r0g * DIM + h * HD + d;
        const size_t i1 = i0 + (size_t)8 * DIM;
        *reinterpret_cast<unsigned*>(&g_oh[i0]) =
            pack2h(o[nt][0] * inv0, o[nt][1] * inv0);
        *reinterpret_cast<unsigned*>(&g_oh[i1]) =
            pack2h(o[nt][2] * inv1, o[nt][3] * inv1);
    }
}

// ---------------- round x / w_qkv / w_proj to fp16 ----------------
#define SEG_X  (LEN * DIM / 4)
#define SEG_WQ (3 * DIM * DIM / 4)
#define SEG_WP (DIM * DIM / 4)
__global__ void split_inputs(const float* __restrict__ x,
                             const float* __restrict__ wq,
                             const float* __restrict__ wp)
{
    const int i = blockIdx.x * blockDim.x + threadIdx.x;
    if (i < SEG_X) {
        float4 v = reinterpret_cast<const float4*>(x)[i];
        reinterpret_cast<uint2*>(g_xh)[i] =
            make_uint2(pack2h(v.x, v.y), pack2h(v.z, v.w));
    } else if (i < SEG_X + SEG_WQ) {
        const int j = i - SEG_X;
        float4 v = reinterpret_cast<const float4*>(wq)[j];
        reinterpret_cast<uint2*>(g_wqh)[j] =
            make_uint2(pack2h(v.x, v.y), pack2h(v.z, v.w));
    } else if (i < SEG_X + SEG_WQ + SEG_WP) {
        const int j = i - SEG_X - SEG_WQ;
        float4 v = reinterpret_cast<const float4*>(wp)[j];
        reinterpret_cast<uint2*>(g_wph)[j] =
            make_uint2(pack2h(v.x, v.y), pack2h(v.z, v.w));
    }
}

// ---------------- QK RMSNorm + RoPE + V transpose (fp16 qkv input) ------------
__global__ void qknorm_rope(const float* __restrict__ pe,
                            const float* __restrict__ qs,
                            const float* __restrict__ ks)
{
    const int l = blockIdx.x;
    const int h = blockIdx.y;
    const int d = threadIdx.x;

    const __half* base = g_qkv + (size_t)l * (3 * DIM) + h * HD;
    float q = __half2float(base[d]);
    float k = __half2float(base[DIM + d]);
    float v = __half2float(base[2 * DIM + d]);

    float sq = q * q, sk = k * k;
#pragma unroll
    for (int o = 16; o; o >>= 1) {
        sq += __shfl_xor_sync(0xffffffffu, sq, o);
        sk += __shfl_xor_sync(0xffffffffu, sk, o);
    }
    __shared__ float rq[4], rk[4];
    const int w = d >> 5;
    if ((d & 31) == 0) { rq[w] = sq; rk[w] = sk; }
    __syncthreads();
    sq = rq[0] + rq[1] + rq[2] + rq[3];
    sk = rk[0] + rk[1] + rk[2] + rk[3];

    const float rrq = rsqrtf(sq * (1.0f / HD) + 1e-6f);
    const float rrk = rsqrtf(sk * (1.0f / HD) + 1e-6f);
    float qn = q * rrq * qs[d];
    float kn = k * rrk * ks[d];

    const float qp = __shfl_xor_sync(0xffffffffu, qn, 1);
    const float kp = __shfl_xor_sync(0xffffffffu, kn, 1);
    const int j = d >> 1, a = d & 1;
    const float* p = pe + (size_t)l * (HD / 2) * 4 + j * 4 + a * 2;
    const float q0 = a ? qp : qn, q1 = a ? qn : qp;
    const float k0 = a ? kp : kn, k1 = a ? kn : kp;
    const float qr = (p[0] * q0 + p[1] * q1) * (SCALE * LOG2E);
    const float kr = p[0] * k0 + p[1] * k1;

    const size_t idx = ((size_t)h * LEN + l) * HD + d;
    g_qh[idx] = __float2half_rn(qr);
    g_kh[idx] = __float2half_rn(kr);
    g_vth[((size_t)h * HD + d) * LEN + l] = __float2half_rn(v);
}

// ---------------- launch ----------------
extern "C" void kernel_launch(void* const* d_in, const int* in_sizes, int n_in,
                              void* d_out, int out_size)
{
    const float* x      = (const float*)d_in[0];
    const float* pe     = (const float*)d_in[1];
    const float* w_qkv  = (const float*)d_in[2];
    const float* q_sc   = (const float*)d_in[3];
    const float* k_sc   = (const float*)d_in[4];
    const float* w_proj = (const float*)d_in[5];
    const float* b_proj = (const float*)d_in[6];
    float* out = (float*)d_out;

    __half *p_qkv, *p_xh, *p_wqh, *p_wph, *p_oh;
    cudaGetSymbolAddress((void**)&p_qkv, g_qkv);
    cudaGetSymbolAddress((void**)&p_xh,  g_xh);
    cudaGetSymbolAddress((void**)&p_wqh, g_wqh);
    cudaGetSymbolAddress((void**)&p_wph, g_wph);
    cudaGetSymbolAddress((void**)&p_oh,  g_oh);

    cudaFuncSetAttribute((const void*)gemm_nt_h2<256, 64, __half>,
                         cudaFuncAttributeMaxDynamicSharedMemorySize, GSMEM_SINGLE);
    cudaFuncSetAttribute((const void*)gemm_nt_h2<256, 64, float>,
                         cudaFuncAttributeMaxDynamicSharedMemorySize, GSMEM_SINGLE);
    cudaFuncSetAttribute((const void*)flash_attn,
                         cudaFuncAttributeMaxDynamicSharedMemorySize, FA_SMEM);

    // 0) round x, weights to fp16
    {
        const int total = SEG_X + SEG_WQ + SEG_WP;
        split_inputs<<<(total + 255) / 256, 256>>>(x, w_qkv, w_proj);
    }

    // 1) QKV = x @ w_qkv^T : [2048, 6144] fp16 output
    gemm_nt_h2<256, 64, __half><<<dim3(6144 / 256, 2048 / 128, 1), 256, GSMEM_SINGLE>>>(
        p_xh, p_wqh, p_qkv, 2048, 2048, 2048, 6144, 1.0f, nullptr);

    // 2) QK RMSNorm + RoPE + V transpose (SCALE*log2e folded into Q)
    qknorm_rope<<<dim3(LEN, NH), HD>>>(pe, q_sc, k_sc);

    // 3) fused attention (no-max softmax, persistent Q, 3-stage K/V, fused exp/PV)
    flash_attn<<<dim3(LEN / 128, NH), 256, FA_SMEM>>>();

    // 4) out = O @ w_proj^T + b_proj : [2048, 2048] fp32
    gemm_nt_h2<256, 64, float><<<dim3(2048 / 256, 2048 / 128, 1), 256, GSMEM_SINGLE>>>(
        p_oh, p_wph, out, 2048, 2048, 2048, 2048, 1.0f, b_proj);
}

// round 15
// speedup vs baseline: 1.0435x; 1.0232x over previous
#include <cuda_runtime.h>
#include <cuda_fp16.h>
#include <math.h>
#include <stdint.h>

#define LEN 2048
#define DIM 2048
#define NH 16
#define HD 128
#define SCALE 0.08838834764831845f   /* 1/sqrt(128) */
#define LOG2E 1.4426950408889634f
#define SOFT_OFF (4.0f * LOG2E)      /* fixed softmax offset, log2 domain */

// ---------------- scratch (allocation-free: __device__ globals) ----------------
__device__ __half g_qkv[(size_t)LEN * 3 * DIM];              // [L, 3*DIM] fp16

__device__ __half g_xh[(size_t)LEN * DIM];                   // x (fp16)
__device__ __half g_wqh[(size_t)3 * DIM * DIM];              // w_qkv (fp16)
__device__ __half g_wph[(size_t)DIM * DIM];                  // w_proj (fp16)
__device__ __half g_qh[(size_t)NH * LEN * HD];               // q*SCALE*log2e [H,L,D]
__device__ __half g_kh[(size_t)NH * LEN * HD];               // k (fp16) [H,L,D]
__device__ __half g_vth[(size_t)NH * HD * LEN];              // v^T (fp16) [H,D,L]
__device__ __half g_oh[(size_t)LEN * DIM];                   // O (fp16) [L, H*D]

// ---------------- helpers ----------------
static __device__ __forceinline__ unsigned cvta_smem(const void* p) {
    return (unsigned)__cvta_generic_to_shared(p);
}
static __device__ __forceinline__ unsigned pack2h(float x0, float x1) {
    __half2 h = __floats2half2_rn(x0, x1);
    return *reinterpret_cast<unsigned*>(&h);
}

#define LDSM4(r0, r1, r2, r3, addr)                                         \
    asm volatile("ldmatrix.sync.aligned.m8n8.x4.shared.b16 {%0,%1,%2,%3}, [%4];" \
                 : "=r"(r0), "=r"(r1), "=r"(r2), "=r"(r3) : "r"(addr))

#define MMA16816(d, a, b0_, b1_)                                            \
    asm volatile("mma.sync.aligned.m16n8k16.row.col.f32.f16.f16.f32 "      \
                 "{%0,%1,%2,%3},{%4,%5,%6,%7},{%8,%9},{%0,%1,%2,%3};"      \
                 : "+f"(d[0]), "+f"(d[1]), "+f"(d[2]), "+f"(d[3])           \
                 : "r"(a[0]), "r"(a[1]), "r"(a[2]), "r"(a[3]),              \
                   "r"(b0_), "r"(b1_))

#define CP_ASYNC16(dst, src) \
    asm volatile("cp.async.cg.shared.global [%0], [%1], 16;" \
                 :: "r"(dst), "l"(src) : "memory")
#define CP_COMMIT() asm volatile("cp.async.commit_group;" ::: "memory")
#define CP_WAIT1()  asm volatile("cp.async.wait_group 1;" ::: "memory")
#define CP_WAIT0()  asm volatile("cp.async.wait_group 0;" ::: "memory")

// ================= generic fp16 NT GEMM (128x128 tile, 2 CTAs/SM) =============
template<int ROWS>
static __device__ __forceinline__ void load_tile(
    unsigned sbase, const __half* __restrict__ A,
    int ld, int kbase, int tid)
{
#pragma unroll
    for (int i = 0; i < ROWS / 32; ++i) {
        const int idx = tid + i * 256;
        const int row = idx >> 3;
        const int ch  = idx & 7;
        const unsigned dst = sbase + row * 128 + ((ch * 16) ^ ((row & 7) * 16));
        const __half* src = A + (long long)row * ld + kbase + ch * 8;
        CP_ASYNC16(dst, src);
    }
}

// C = alpha * A @ B^T (+bias). OUT = float or __half.
// CTA tile 128x128, 256 threads, 8 warps 2(m)x4(n), warp tile 64x32,
// BK=64, 3-stage cp.async, 1 sync/chunk, 2 CTAs/SM (regs <= 128).
template<typename OUT>
__global__ __launch_bounds__(256, 2)
void gemm_nt_h2(const __half* __restrict__ Ah,
                const __half* __restrict__ Bh,
                OUT* __restrict__ C,
                int K, int lda, int ldb, int ldc,
                float alpha, const float* __restrict__ bias)
{
    constexpr int NT16  = 2;           // WN=32
    constexpr int AT    = 128 * 64 * 2;
    constexpr int BT    = 128 * 64 * 2;
    constexpr int STAGE = AT + BT;     // 32768

    extern __shared__ char smem[];
    const unsigned smem_b = cvta_smem(smem);

    const int tid  = threadIdx.x;
    const int wid  = tid >> 5;
    const int lane = tid & 31;
    const int wm = (wid >> 2) * 64;
    const int wn = (wid & 3) * 32;
    const int m0 = blockIdx.y * 128;
    const int n0 = blockIdx.x * 128;

    const __half* pAh = Ah + (long long)m0 * lda;
    const __half* pBh = Bh + (long long)n0 * ldb;

    unsigned offA0[4], mskA[4];
    const unsigned cbA = ((lane >> 4) & 1) * 16;
#pragma unroll
    for (int mt = 0; mt < 4; ++mt) {
        const int r = wm + mt * 16 + (lane & 15);
        offA0[mt] = r * 128;
        mskA[mt]  = (r & 7) * 16;
    }
    unsigned offB0[NT16], mskB[NT16];
    const unsigned cbB = ((lane >> 3) & 1) * 16;
#pragma unroll
    for (int p = 0; p < NT16; ++p) {
        const int r = wn + p * 16 + (lane & 7) + ((lane >> 4) & 1) * 8;
        offB0[p] = r * 128;
        mskB[p]  = (r & 7) * 16;
    }

    float acc[4][2 * NT16][4];
#pragma unroll
    for (int i = 0; i < 4; ++i)
#pragma unroll
        for (int j = 0; j < 2 * NT16; ++j)
#pragma unroll
            for (int v = 0; v < 4; ++v) acc[i][j][v] = 0.0f;

    const int nch = K >> 6;

#pragma unroll
    for (int pc = 0; pc < 2; ++pc) {
        const unsigned sb = smem_b + pc * STAGE;
        const int kb = pc * 64;
        load_tile<128>(sb, pAh, lda, kb, tid);
        load_tile<128>(sb + AT, pBh, ldb, kb, tid);
        CP_COMMIT();
    }

    for (int c = 0; c < nch; ++c) {
        if (c + 1 < nch) { CP_WAIT1(); } else { CP_WAIT0(); }
        __syncthreads();

        if (c + 2 < nch) {
            const unsigned sb2 = smem_b + ((c + 2) % 3) * STAGE;
            const int kb = (c + 2) * 64;
            load_tile<128>(sb2, pAh, lda, kb, tid);
            load_tile<128>(sb2 + AT, pBh, ldb, kb, tid);
            CP_COMMIT();
        }

        const unsigned sb = smem_b + (c % 3) * STAGE;
#pragma unroll
        for (int ks = 0; ks < 4; ++ks) {
            const unsigned kb = ks * 32;
            unsigned ah[4][4];
#pragma unroll
            for (int mt = 0; mt < 4; ++mt) {
                const unsigned a0 = sb + offA0[mt] + ((cbA + kb) ^ mskA[mt]);
                LDSM4(ah[mt][0], ah[mt][1], ah[mt][2], ah[mt][3], a0);
            }
#pragma unroll
            for (int p = 0; p < NT16; ++p) {
                const unsigned b0 = sb + AT + offB0[p] + ((cbB + kb) ^ mskB[p]);
                unsigned bh[4];
                LDSM4(bh[0], bh[1], bh[2], bh[3], b0);
#pragma unroll
                for (int mt = 0; mt < 4; ++mt) {
                    MMA16816(acc[mt][2 * p],     ah[mt], bh[0], bh[1]);
                    MMA16816(acc[mt][2 * p + 1], ah[mt], bh[2], bh[3]);
                }
            }
        }
    }

    const int g  = lane >> 2;
    const int tg = lane & 3;
#pragma unroll
    for (int mt = 0; mt < 4; ++mt) {
#pragma unroll
        for (int nt = 0; nt < 2 * NT16; ++nt) {
            const int r = m0 + wm + mt * 16 + g;
            const int c = n0 + wn + nt * 8 + tg * 2;
            float bx = 0.0f, by = 0.0f;
            if (bias) { bx = bias[c]; by = bias[c + 1]; }
            const float v00 = acc[mt][nt][0] * alpha + bx;
            const float v01 = acc[mt][nt][1] * alpha + by;
            const float v10 = acc[mt][nt][2] * alpha + bx;
            const float v11 = acc[mt][nt][3] * alpha + by;
            if (sizeof(OUT) == 4) {
                *reinterpret_cast<float2*>((float*)C + (long long)r * ldc + c) =
                    make_float2(v00, v01);
                *reinterpret_cast<float2*>((float*)C + (long long)(r + 8) * ldc + c) =
                    make_float2(v10, v11);
            } else {
                *reinterpret_cast<unsigned*>((__half*)C + (long long)r * ldc + c) =
                    pack2h(v00, v01);
                *reinterpret_cast<unsigned*>((__half*)C + (long long)(r + 8) * ldc + c) =
                    pack2h(v10, v11);
            }
        }
    }
}

#define GSMEM (3 * 32768)   /* 98304: 2 CTAs/SM */

// ================= flash attention (round-14 best) =================
// grid (16 q-blocks, 16 heads), 256 threads (8 warps), each warp owns 16 q rows.
// smem: Q 32K | K 3x32K | V 3x32K = 224KB. No-max softmax (QKNorm bound),
// exp2 domain, persistent Q fragments, 3-stage K/V, one barrier/iter.
#define FA_SMEM (224 * 1024)

static __device__ __forceinline__ void fa_load(
    unsigned dst, const __half* __restrict__ src, int ld, int tid)
{
#pragma unroll
    for (int i = 0; i < 8; ++i) {
        const int idx = tid + i * 256;
        const int row = idx >> 4;
        const int ch  = idx & 15;
        const unsigned d = dst + row * 256 + ((ch * 16) ^ ((row & 7) * 16));
        CP_ASYNC16(d, src + (long long)row * ld + ch * 8);
    }
}

__global__ __launch_bounds__(256, 1)
void flash_attn()
{
    extern __shared__ char smem[];
    const unsigned sb  = cvta_smem(smem);
    const unsigned sQ  = sb;
    const unsigned sK  = sb + 32768;
    const unsigned sV  = sb + 131072;

    const int tid  = threadIdx.x;
    const int wid  = tid >> 5;
    const int lane = tid & 31;
    const int qb = blockIdx.x;
    const int h  = blockIdx.y;

    const __half* Qh = g_qh + ((size_t)h * LEN + qb * 128) * HD;
    const __half* Kh = g_kh + (size_t)h * LEN * HD;
    const __half* Vt = g_vth + (size_t)h * HD * LEN;

    fa_load(sQ, Qh, HD, tid);
    fa_load(sK, Kh, HD, tid);
    fa_load(sV, Vt, LEN, tid);
    CP_COMMIT();
    fa_load(sK + 32768, Kh + 128 * HD, HD, tid);
    fa_load(sV + 32768, Vt + 128, LEN, tid);
    CP_COMMIT();

    const int q0 = wid * 16;
    const unsigned rowA256 = (q0 + (lane & 15)) * 256;
    const unsigned mskA    = (lane & 7) * 16;
    const unsigned caA     = ((lane >> 4) & 1) * 16;
    const int rB0          = (lane & 7) + ((lane >> 4) & 1) * 8;
    const unsigned rowB256 = rB0 * 256;
    const unsigned mskB    = (rB0 & 7) * 16;
    const unsigned cbB     = ((lane >> 3) & 1) * 16;

    CP_WAIT1();
    __syncthreads();
    unsigned aq[8][4];
#pragma unroll
    for (int kd = 0; kd < 8; ++kd) {
        const unsigned ca = (kd * 32 + caA) ^ mskA;
        LDSM4(aq[kd][0], aq[kd][1], aq[kd][2], aq[kd][3], sQ + rowA256 + ca);
    }

    float o[16][4];
#pragma unroll
    for (int i = 0; i < 16; ++i)
#pragma unroll
        for (int v = 0; v < 4; ++v) o[i][v] = 0.0f;
    float l0 = 0.0f, l1 = 0.0f;

    const int NB = LEN / 128;
    int stage = 0;
    for (int j = 0; j < NB; ++j) {
        if (j > 0) {
            if (j + 1 < NB) { CP_WAIT1(); } else { CP_WAIT0(); }
            __syncthreads();
        }

        if (j + 2 < NB) {
            const int s2 = (stage + 2 >= 3) ? stage - 1 : stage + 2;
            fa_load(sK + s2 * 32768, Kh + (long long)(j + 2) * 128 * HD, HD, tid);
            fa_load(sV + s2 * 32768, Vt + (j + 2) * 128, LEN, tid);
            CP_COMMIT();
        }

        const unsigned kbuf = sK + stage * 32768;
        const unsigned vbuf = sV + stage * 32768;
        stage = (stage + 1 == 3) ? 0 : stage + 1;

        float s[16][4];
#pragma unroll
        for (int i = 0; i < 16; ++i)
#pragma unroll
            for (int v = 0; v < 4; ++v) s[i][v] = -SOFT_OFF;

#pragma unroll
        for (int kd = 0; kd < 8; ++kd) {
            const unsigned cb = (kd * 32 + cbB) ^ mskB;
#pragma unroll
            for (int p = 0; p < 8; ++p) {
                unsigned bk[4];
                LDSM4(bk[0], bk[1], bk[2], bk[3], kbuf + rowB256 + p * 4096 + cb);
                MMA16816(s[2 * p],     aq[kd], bk[0], bk[1]);
                MMA16816(s[2 * p + 1], aq[kd], bk[2], bk[3]);
            }
        }

#pragma unroll
        for (int kt = 0; kt < 8; ++kt) {
            const float e00 = exp2f(s[2 * kt][0]);
            const float e01 = exp2f(s[2 * kt][1]);
            const float e02 = exp2f(s[2 * kt][2]);
            const float e03 = exp2f(s[2 * kt][3]);
            const float e10 = exp2f(s[2 * kt + 1][0]);
            const float e11 = exp2f(s[2 * kt + 1][1]);
            const float e12 = exp2f(s[2 * kt + 1][2]);
            const float e13 = exp2f(s[2 * kt + 1][3]);
            l0 += e00; l0 += e01; l1 += e02; l1 += e03;
            l0 += e10; l0 += e11; l1 += e12; l1 += e13;
            unsigned ph[4];
            ph[0] = pack2h(e00, e01);
            ph[1] = pack2h(e02, e03);
            ph[2] = pack2h(e10, e11);
            ph[3] = pack2h(e12, e13);

            const unsigned cb = (kt * 32 + cbB) ^ mskB;
#pragma unroll
            for (int dt = 0; dt < 8; ++dt) {
                unsigned bv[4];
                LDSM4(bv[0], bv[1], bv[2], bv[3], vbuf + rowB256 + dt * 4096 + cb);
                MMA16816(o[2 * dt],     ph, bv[0], bv[1]);
                MMA16816(o[2 * dt + 1], ph, bv[2], bv[3]);
            }
        }
    }

    l0 += __shfl_xor_sync(0xffffffffu, l0, 1);
    l0 += __shfl_xor_sync(0xffffffffu, l0, 2);
    l1 += __shfl_xor_sync(0xffffffffu, l1, 1);
    l1 += __shfl_xor_sync(0xffffffffu, l1, 2);
    const float inv0 = 1.0f / l0;
    const float inv1 = 1.0f / l1;

    const int r0g = qb * 128 + q0 + (lane >> 2);
#pragma unroll
    for (int nt = 0; nt < 16; ++nt) {
        const int d = nt * 8 + (lane & 3) * 2;
        const size_t i0 = (size_t)r0g * DIM + h * HD + d;
        const size_t i1 = i0 + (size_t)8 * DIM;
        *reinterpret_cast<unsigned*>(&g_oh[i0]) =
            pack2h(o[nt][0] * inv0, o[nt][1] * inv0);
        *reinterpret_cast<unsigned*>(&g_oh[i1]) =
            pack2h(o[nt][2] * inv1, o[nt][3] * inv1);
    }
}

// ---------------- round x / w_qkv / w_proj to fp16 ----------------
#define SEG_X  (LEN * DIM / 4)
#define SEG_WQ (3 * DIM * DIM / 4)
#define SEG_WP (DIM * DIM / 4)
__global__ void split_inputs(const float* __restrict__ x,
                             const float* __restrict__ wq,
                             const float* __restrict__ wp)
{
    const int i = blockIdx.x * blockDim.x + threadIdx.x;
    if (i < SEG_X) {
        float4 v = reinterpret_cast<const float4*>(x)[i];
        reinterpret_cast<uint2*>(g_xh)[i] =
            make_uint2(pack2h(v.x, v.y), pack2h(v.z, v.w));
    } else if (i < SEG_X + SEG_WQ) {
        const int j = i - SEG_X;
        float4 v = reinterpret_cast<const float4*>(wq)[j];
        reinterpret_cast<uint2*>(g_wqh)[j] =
            make_uint2(pack2h(v.x, v.y), pack2h(v.z, v.w));
    } else if (i < SEG_X + SEG_WQ + SEG_WP) {
        const int j = i - SEG_X - SEG_WQ;
        float4 v = reinterpret_cast<const float4*>(wp)[j];
        reinterpret_cast<uint2*>(g_wph)[j] =
            make_uint2(pack2h(v.x, v.y), pack2h(v.z, v.w));
    }
}

// ---------------- QK RMSNorm + RoPE + V transpose (fp16 qkv input) ------------
__global__ void qknorm_rope(const float* __restrict__ pe,
                            const float* __restrict__ qs,
                            const float* __restrict__ ks)
{
    const int l = blockIdx.x;
    const int h = blockIdx.y;
    const int d = threadIdx.x;

    const __half* base = g_qkv + (size_t)l * (3 * DIM) + h * HD;
    float q = __half2float(base[d]);
    float k = __half2float(base[DIM + d]);
    float v = __half2float(base[2 * DIM + d]);

    float sq = q * q, sk = k * k;
#pragma unroll
    for (int o = 16; o; o >>= 1) {
        sq += __shfl_xor_sync(0xffffffffu, sq, o);
        sk += __shfl_xor_sync(0xffffffffu, sk, o);
    }
    __shared__ float rq[4], rk[4];
    const int w = d >> 5;
    if ((d & 31) == 0) { rq[w] = sq; rk[w] = sk; }
    __syncthreads();
    sq = rq[0] + rq[1] + rq[2] + rq[3];
    sk = rk[0] + rk[1] + rk[2] + rk[3];

    const float rrq = rsqrtf(sq * (1.0f / HD) + 1e-6f);
    const float rrk = rsqrtf(sk * (1.0f / HD) + 1e-6f);
    float qn = q * rrq * qs[d];
    float kn = k * rrk * ks[d];

    const float qp = __shfl_xor_sync(0xffffffffu, qn, 1);
    const float kp = __shfl_xor_sync(0xffffffffu, kn, 1);
    const int j = d >> 1, a = d & 1;
    const float* p = pe + (size_t)l * (HD / 2) * 4 + j * 4 + a * 2;
    const float q0 = a ? qp : qn, q1 = a ? qn : qp;
    const float k0 = a ? kp : kn, k1 = a ? kn : kp;
    const float qr = (p[0] * q0 + p[1] * q1) * (SCALE * LOG2E);
    const float kr = p[0] * k0 + p[1] * k1;

    const size_t idx = ((size_t)h * LEN + l) * HD + d;
    g_qh[idx] = __float2half_rn(qr);
    g_kh[idx] = __float2half_rn(kr);
    g_vth[((size_t)h * HD + d) * LEN + l] = __float2half_rn(v);
}

// ---------------- launch ----------------
extern "C" void kernel_launch(void* const* d_in, const int* in_sizes, int n_in,
                              void* d_out, int out_size)
{
    const float* x      = (const float*)d_in[0];
    const float* pe     = (const float*)d_in[1];
    const float* w_qkv  = (const float*)d_in[2];
    const float* q_sc   = (const float*)d_in[3];
    const float* k_sc   = (const float*)d_in[4];
    const float* w_proj = (const float*)d_in[5];
    const float* b_proj = (const float*)d_in[6];
    float* out = (float*)d_out;

    __half *p_qkv, *p_xh, *p_wqh, *p_wph, *p_oh;
    cudaGetSymbolAddress((void**)&p_qkv, g_qkv);
    cudaGetSymbolAddress((void**)&p_xh,  g_xh);
    cudaGetSymbolAddress((void**)&p_wqh, g_wqh);
    cudaGetSymbolAddress((void**)&p_wph, g_wph);
    cudaGetSymbolAddress((void**)&p_oh,  g_oh);

    cudaFuncSetAttribute((const void*)gemm_nt_h2<__half>,
                         cudaFuncAttributeMaxDynamicSharedMemorySize, GSMEM);
    cudaFuncSetAttribute((const void*)gemm_nt_h2<float>,
                         cudaFuncAttributeMaxDynamicSharedMemorySize, GSMEM);
    cudaFuncSetAttribute((const void*)flash_attn,
                         cudaFuncAttributeMaxDynamicSharedMemorySize, FA_SMEM);

    // 0) round x, weights to fp16
    {
        const int total = SEG_X + SEG_WQ + SEG_WP;
        split_inputs<<<(total + 255) / 256, 256>>>(x, w_qkv, w_proj);
    }

    // 1) QKV = x @ w_qkv^T : [2048, 6144] fp16 output
    gemm_nt_h2<__half><<<dim3(6144 / 128, 2048 / 128, 1), 256, GSMEM>>>(
        p_xh, p_wqh, p_qkv, 2048, 2048, 2048, 6144, 1.0f, nullptr);

    // 2) QK RMSNorm + RoPE + V transpose (SCALE*log2e folded into Q)
    qknorm_rope<<<dim3(LEN, NH), HD>>>(pe, q_sc, k_sc);

    // 3) fused attention (no-max softmax, persistent Q, 3-stage K/V)
    flash_attn<<<dim3(LEN / 128, NH), 256, FA_SMEM>>>();

    // 4) out = O @ w_proj^T + b_proj : [2048, 2048] fp32
    gemm_nt_h2<float><<<dim3(2048 / 128, 2048 / 128, 1), 256, GSMEM>>>(
        p_oh, p_wph, out, 2048, 2048, 2048, 2048, 1.0f, b_proj);
}

// round 16
// speedup vs baseline: 1.0558x; 1.0118x over previous
#include <cuda_runtime.h>
#include <cuda_fp16.h>
#include <math.h>
#include <stdint.h>

#define LEN 2048
#define DIM 2048
#define NH 16
#define HD 128
#define SCALE 0.08838834764831845f   /* 1/sqrt(128) */
#define LOG2E 1.4426950408889634f
#define SOFT_OFF (4.0f * LOG2E)      /* fixed softmax offset, log2 domain */

// ---------------- scratch (allocation-free: __device__ globals) ----------------
__device__ __half g_qkv[(size_t)LEN * 3 * DIM];              // [L, 3*DIM] fp16

__device__ __half g_xh[(size_t)LEN * DIM];                   // x (fp16)
__device__ __half g_wqh[(size_t)3 * DIM * DIM];              // w_qkv (fp16)
__device__ __half g_wph[(size_t)DIM * DIM];                  // w_proj (fp16)
__device__ __half g_qh[(size_t)NH * LEN * HD];               // q*SCALE*log2e [H,L,D]
__device__ __half g_kh[(size_t)NH * LEN * HD];               // k (fp16) [H,L,D]
__device__ __half g_vth[(size_t)NH * HD * LEN];              // v^T (fp16) [H,D,L]
__device__ __half g_oh[(size_t)LEN * DIM];                   // O (fp16) [L, H*D]

// ---------------- helpers ----------------
static __device__ __forceinline__ unsigned cvta_smem(const void* p) {
    return (unsigned)__cvta_generic_to_shared(p);
}
static __device__ __forceinline__ unsigned pack2h(float x0, float x1) {
    __half2 h = __floats2half2_rn(x0, x1);
    return *reinterpret_cast<unsigned*>(&h);
}

#define LDSM4(r0, r1, r2, r3, addr)                                         \
    asm volatile("ldmatrix.sync.aligned.m8n8.x4.shared.b16 {%0,%1,%2,%3}, [%4];" \
                 : "=r"(r0), "=r"(r1), "=r"(r2), "=r"(r3) : "r"(addr))

#define MMA16816(d, a, b0_, b1_)                                            \
    asm volatile("mma.sync.aligned.m16n8k16.row.col.f32.f16.f16.f32 "      \
                 "{%0,%1,%2,%3},{%4,%5,%6,%7},{%8,%9},{%0,%1,%2,%3};"      \
                 : "+f"(d[0]), "+f"(d[1]), "+f"(d[2]), "+f"(d[3])           \
                 : "r"(a[0]), "r"(a[1]), "r"(a[2]), "r"(a[3]),              \
                   "r"(b0_), "r"(b1_))

#define CP_ASYNC16(dst, src) \
    asm volatile("cp.async.cg.shared.global [%0], [%1], 16;" \
                 :: "r"(dst), "l"(src) : "memory")
#define CP_COMMIT() asm volatile("cp.async.commit_group;" ::: "memory")
#define CP_WAIT1()  asm volatile("cp.async.wait_group 1;" ::: "memory")
#define CP_WAIT0()  asm volatile("cp.async.wait_group 0;" ::: "memory")

// ================= generic fp16 NT GEMM (128x128 tile, 2 CTAs/SM) =============
template<int ROWS>
static __device__ __forceinline__ void load_tile(
    unsigned sbase, const __half* __restrict__ A,
    int ld, int kbase, int tid)
{
#pragma unroll
    for (int i = 0; i < ROWS / 32; ++i) {
        const int idx = tid + i * 256;
        const int row = idx >> 3;
        const int ch  = idx & 7;
        const unsigned dst = sbase + row * 128 + ((ch * 16) ^ ((row & 7) * 16));
        const __half* src = A + (long long)row * ld + kbase + ch * 8;
        CP_ASYNC16(dst, src);
    }
}

template<typename OUT>
__global__ __launch_bounds__(256, 2)
void gemm_nt_h2(const __half* __restrict__ Ah,
                const __half* __restrict__ Bh,
                OUT* __restrict__ C,
                int K, int lda, int ldb, int ldc,
                float alpha, const float* __restrict__ bias)
{
    constexpr int NT16  = 2;           // WN=32
    constexpr int AT    = 128 * 64 * 2;
    constexpr int BT    = 128 * 64 * 2;
    constexpr int STAGE = AT + BT;     // 32768

    extern __shared__ char smem[];
    const unsigned smem_b = cvta_smem(smem);

    const int tid  = threadIdx.x;
    const int wid  = tid >> 5;
    const int lane = tid & 31;
    const int wm = (wid >> 2) * 64;
    const int wn = (wid & 3) * 32;
    const int m0 = blockIdx.y * 128;
    const int n0 = blockIdx.x * 128;

    const __half* pAh = Ah + (long long)m0 * lda;
    const __half* pBh = Bh + (long long)n0 * ldb;

    unsigned offA0[4], mskA[4];
    const unsigned cbA = ((lane >> 4) & 1) * 16;
#pragma unroll
    for (int mt = 0; mt < 4; ++mt) {
        const int r = wm + mt * 16 + (lane & 15);
        offA0[mt] = r * 128;
        mskA[mt]  = (r & 7) * 16;
    }
    unsigned offB0[NT16], mskB[NT16];
    const unsigned cbB = ((lane >> 3) & 1) * 16;
#pragma unroll
    for (int p = 0; p < NT16; ++p) {
        const int r = wn + p * 16 + (lane & 7) + ((lane >> 4) & 1) * 8;
        offB0[p] = r * 128;
        mskB[p]  = (r & 7) * 16;
    }

    float acc[4][2 * NT16][4];
#pragma unroll
    for (int i = 0; i < 4; ++i)
#pragma unroll
        for (int j = 0; j < 2 * NT16; ++j)
#pragma unroll
            for (int v = 0; v < 4; ++v) acc[i][j][v] = 0.0f;

    const int nch = K >> 6;

#pragma unroll
    for (int pc = 0; pc < 2; ++pc) {
        const unsigned sb = smem_b + pc * STAGE;
        const int kb = pc * 64;
        load_tile<128>(sb, pAh, lda, kb, tid);
        load_tile<128>(sb + AT, pBh, ldb, kb, tid);
        CP_COMMIT();
    }

    for (int c = 0; c < nch; ++c) {
        if (c + 1 < nch) { CP_WAIT1(); } else { CP_WAIT0(); }
        __syncthreads();

        if (c + 2 < nch) {
            const unsigned sb2 = smem_b + ((c + 2) % 3) * STAGE;
            const int kb = (c + 2) * 64;
            load_tile<128>(sb2, pAh, lda, kb, tid);
            load_tile<128>(sb2 + AT, pBh, ldb, kb, tid);
            CP_COMMIT();
        }

        const unsigned sb = smem_b + (c % 3) * STAGE;
#pragma unroll
        for (int ks = 0; ks < 4; ++ks) {
            const unsigned kb = ks * 32;
            unsigned ah[4][4];
#pragma unroll
            for (int mt = 0; mt < 4; ++mt) {
                const unsigned a0 = sb + offA0[mt] + ((cbA + kb) ^ mskA[mt]);
                LDSM4(ah[mt][0], ah[mt][1], ah[mt][2], ah[mt][3], a0);
            }
#pragma unroll
            for (int p = 0; p < NT16; ++p) {
                const unsigned b0 = sb + AT + offB0[p] + ((cbB + kb) ^ mskB[p]);
                unsigned bh[4];
                LDSM4(bh[0], bh[1], bh[2], bh[3], b0);
#pragma unroll
                for (int mt = 0; mt < 4; ++mt) {
                    MMA16816(acc[mt][2 * p],     ah[mt], bh[0], bh[1]);
                    MMA16816(acc[mt][2 * p + 1], ah[mt], bh[2], bh[3]);
                }
            }
        }
    }

    const int g  = lane >> 2;
    const int tg = lane & 3;
#pragma unroll
    for (int mt = 0; mt < 4; ++mt) {
#pragma unroll
        for (int nt = 0; nt < 2 * NT16; ++nt) {
            const int r = m0 + wm + mt * 16 + g;
            const int c = n0 + wn + nt * 8 + tg * 2;
            float bx = 0.0f, by = 0.0f;
            if (bias) { bx = bias[c]; by = bias[c + 1]; }
            const float v00 = acc[mt][nt][0] * alpha + bx;
            const float v01 = acc[mt][nt][1] * alpha + by;
            const float v10 = acc[mt][nt][2] * alpha + bx;
            const float v11 = acc[mt][nt][3] * alpha + by;
            if (sizeof(OUT) == 4) {
                *reinterpret_cast<float2*>((float*)C + (long long)r * ldc + c) =
                    make_float2(v00, v01);
                *reinterpret_cast<float2*>((float*)C + (long long)(r + 8) * ldc + c) =
                    make_float2(v10, v11);
            } else {
                *reinterpret_cast<unsigned*>((__half*)C + (long long)r * ldc + c) =
                    pack2h(v00, v01);
                *reinterpret_cast<unsigned*>((__half*)C + (long long)(r + 8) * ldc + c) =
                    pack2h(v10, v11);
            }
        }
    }
}

#define GSMEM (3 * 32768)   /* 98304: 2 CTAs/SM */

// ================= flash attention =================
// grid (16 q-blocks, 16 heads), 256 threads (8 warps), each warp owns 16 q rows.
// smem: Q 32K | K 3x32K | V 3x32K = 224KB. No-max softmax (QKNorm bound),
// f16x2 exp2 (half the MUFU issue), persistent Q fragments, 3-stage K/V,
// one barrier per iteration.
#define FA_SMEM (224 * 1024)

static __device__ __forceinline__ void fa_load(
    unsigned dst, const __half* __restrict__ src, int ld, int tid)
{
#pragma unroll
    for (int i = 0; i < 8; ++i) {
        const int idx = tid + i * 256;
        const int row = idx >> 4;
        const int ch  = idx & 15;
        const unsigned d = dst + row * 256 + ((ch * 16) ^ ((row & 7) * 16));
        CP_ASYNC16(d, src + (long long)row * ld + ch * 8);
    }
}

__global__ __launch_bounds__(256, 1)
void flash_attn()
{
    extern __shared__ char smem[];
    const unsigned sb  = cvta_smem(smem);
    const unsigned sQ  = sb;
    const unsigned sK  = sb + 32768;
    const unsigned sV  = sb + 131072;

    const int tid  = threadIdx.x;
    const int wid  = tid >> 5;
    const int lane = tid & 31;
    const int qb = blockIdx.x;
    const int h  = blockIdx.y;

    const __half* Qh = g_qh + ((size_t)h * LEN + qb * 128) * HD;
    const __half* Kh = g_kh + (size_t)h * LEN * HD;
    const __half* Vt = g_vth + (size_t)h * HD * LEN;

    fa_load(sQ, Qh, HD, tid);
    fa_load(sK, Kh, HD, tid);
    fa_load(sV, Vt, LEN, tid);
    CP_COMMIT();
    fa_load(sK + 32768, Kh + 128 * HD, HD, tid);
    fa_load(sV + 32768, Vt + 128, LEN, tid);
    CP_COMMIT();

    const int q0 = wid * 16;
    const unsigned rowA256 = (q0 + (lane & 15)) * 256;
    const unsigned mskA    = (lane & 7) * 16;
    const unsigned caA     = ((lane >> 4) & 1) * 16;
    const int rB0          = (lane & 7) + ((lane >> 4) & 1) * 8;
    const unsigned rowB256 = rB0 * 256;
    const unsigned mskB    = (rB0 & 7) * 16;
    const unsigned cbB     = ((lane >> 3) & 1) * 16;

    CP_WAIT1();
    __syncthreads();
    unsigned aq[8][4];
#pragma unroll
    for (int kd = 0; kd < 8; ++kd) {
        const unsigned ca = (kd * 32 + caA) ^ mskA;
        LDSM4(aq[kd][0], aq[kd][1], aq[kd][2], aq[kd][3], sQ + rowA256 + ca);
    }

    float o[16][4];
#pragma unroll
    for (int i = 0; i < 16; ++i)
#pragma unroll
        for (int v = 0; v < 4; ++v) o[i][v] = 0.0f;
    float l0 = 0.0f, l1 = 0.0f;

    const int NB = LEN / 128;
    int stage = 0;
    for (int j = 0; j < NB; ++j) {
        if (j > 0) {
            if (j + 1 < NB) { CP_WAIT1(); } else { CP_WAIT0(); }
            __syncthreads();
        }

        if (j + 2 < NB) {
            const int s2 = (stage + 2 >= 3) ? stage - 1 : stage + 2;
            fa_load(sK + s2 * 32768, Kh + (long long)(j + 2) * 128 * HD, HD, tid);
            fa_load(sV + s2 * 32768, Vt + (j + 2) * 128, LEN, tid);
            CP_COMMIT();
        }

        const unsigned kbuf = sK + stage * 32768;
        const unsigned vbuf = sV + stage * 32768;
        stage = (stage + 1 == 3) ? 0 : stage + 1;

        // ---- S = Q @ K^T + (-offset), log2 domain ----
        float s[16][4];
#pragma unroll
        for (int i = 0; i < 16; ++i)
#pragma unroll
            for (int v = 0; v < 4; ++v) s[i][v] = -SOFT_OFF;

#pragma unroll
        for (int kd = 0; kd < 8; ++kd) {
            const unsigned cb = (kd * 32 + cbB) ^ mskB;
#pragma unroll
            for (int p = 0; p < 8; ++p) {
                unsigned bk[4];
                LDSM4(bk[0], bk[1], bk[2], bk[3], kbuf + rowB256 + p * 4096 + cb);
                MMA16816(s[2 * p],     aq[kd], bk[0], bk[1]);
                MMA16816(s[2 * p + 1], aq[kd], bk[2], bk[3]);
            }
        }

        // ---- f16x2 exp2 + row-sum + PV per key-16 tile ----
#pragma unroll
        for (int kt = 0; kt < 8; ++kt) {
            unsigned in0 = pack2h(s[2 * kt][0],     s[2 * kt][1]);
            unsigned in1 = pack2h(s[2 * kt][2],     s[2 * kt][3]);
            unsigned in2 = pack2h(s[2 * kt + 1][0], s[2 * kt + 1][1]);
            unsigned in3 = pack2h(s[2 * kt + 1][2], s[2 * kt + 1][3]);
            unsigned ph[4];
            asm("ex2.approx.f16x2 %0, %1;" : "=r"(ph[0]) : "r"(in0));
            asm("ex2.approx.f16x2 %0, %1;" : "=r"(ph[1]) : "r"(in1));
            asm("ex2.approx.f16x2 %0, %1;" : "=r"(ph[2]) : "r"(in2));
            asm("ex2.approx.f16x2 %0, %1;" : "=r"(ph[3]) : "r"(in3));

            // rows r: ph[0], ph[2] -> l0 ; rows r+8: ph[1], ph[3] -> l1
            __half2 a0 = __hadd2(*reinterpret_cast<__half2*>(&ph[0]),
                                 *reinterpret_cast<__half2*>(&ph[2]));
            __half2 a1 = __hadd2(*reinterpret_cast<__half2*>(&ph[1]),
                                 *reinterpret_cast<__half2*>(&ph[3]));
            float2 f0 = __half22float2(a0);
            float2 f1 = __half22float2(a1);
            l0 += f0.x + f0.y;
            l1 += f1.x + f1.y;

            const unsigned cb = (kt * 32 + cbB) ^ mskB;
#pragma unroll
            for (int dt = 0; dt < 8; ++dt) {
                unsigned bv[4];
                LDSM4(bv[0], bv[1], bv[2], bv[3], vbuf + rowB256 + dt * 4096 + cb);
                MMA16816(o[2 * dt],     ph, bv[0], bv[1]);
                MMA16816(o[2 * dt + 1], ph, bv[2], bv[3]);
            }
        }
    }

    l0 += __shfl_xor_sync(0xffffffffu, l0, 1);
    l0 += __shfl_xor_sync(0xffffffffu, l0, 2);
    l1 += __shfl_xor_sync(0xffffffffu, l1, 1);
    l1 += __shfl_xor_sync(0xffffffffu, l1, 2);
    const float inv0 = 1.0f / l0;
    const float inv1 = 1.0f / l1;

    const int r0g = qb * 128 + q0 + (lane >> 2);
#pragma unroll
    for (int nt = 0; nt < 16; ++nt) {
        const int d = nt * 8 + (lane & 3) * 2;
        const size_t i0 = (size_t)r0g * DIM + h * HD + d;
        const size_t i1 = i0 + (size_t)8 * DIM;
        __half2 p0 = *reinterpret_cast<__half2*>(&o[nt][0]);  // placeholder (unused)
        (void)p0;
        *reinterpret_cast<unsigned*>(&g_oh[i0]) =
            pack2h(o[nt][0] * inv0, o[nt][1] * inv0);
        *reinterpret_cast<unsigned*>(&g_oh[i1]) =
            pack2h(o[nt][2] * inv1, o[nt][3] * inv1);
    }
}

// ---------------- round x / w_qkv / w_proj to fp16 ----------------
#define SEG_X  (LEN * DIM / 4)
#define SEG_WQ (3 * DIM * DIM / 4)
#define SEG_WP (DIM * DIM / 4)
__global__ void split_inputs(const float* __restrict__ x,
                             const float* __restrict__ wq,
                             const float* __restrict__ wp)
{
    const int i = blockIdx.x * blockDim.x + threadIdx.x;
    if (i < SEG_X) {
        float4 v = reinterpret_cast<const float4*>(x)[i];
        reinterpret_cast<uint2*>(g_xh)[i] =
            make_uint2(pack2h(v.x, v.y), pack2h(v.z, v.w));
    } else if (i < SEG_X + SEG_WQ) {
        const int j = i - SEG_X;
        float4 v = reinterpret_cast<const float4*>(wq)[j];
        reinterpret_cast<uint2*>(g_wqh)[j] =
            make_uint2(pack2h(v.x, v.y), pack2h(v.z, v.w));
    } else if (i < SEG_X + SEG_WQ + SEG_WP) {
        const int j = i - SEG_X - SEG_WQ;
        float4 v = reinterpret_cast<const float4*>(wp)[j];
        reinterpret_cast<uint2*>(g_wph)[j] =
            make_uint2(pack2h(v.x, v.y), pack2h(v.z, v.w));
    }
}

// ---------------- QK RMSNorm + RoPE + V transpose ----------------
// grid 2048 (l), block 512: warp w = head w; lane owns dims 4*lane..4*lane+3.
// shfl-only reductions, in-thread RoPE pairs, vectorized 8B loads/stores.
__global__ __launch_bounds__(512, 2)
void qknorm_rope(const float* __restrict__ pe,
                 const float* __restrict__ qs,
                 const float* __restrict__ ks)
{
    const int l = blockIdx.x;
    const int h = threadIdx.x >> 5;
    const int lane = threadIdx.x & 31;
    const int d0 = lane * 4;

    const __half* base = g_qkv + (size_t)l * (3 * DIM) + h * HD + d0;
    __half2 qv[2], kv[2], vv[2];
    *reinterpret_cast<uint2*>(qv) = *reinterpret_cast<const uint2*>(base);
    *reinterpret_cast<uint2*>(kv) = *reinterpret_cast<const uint2*>(base + DIM);
    *reinterpret_cast<uint2*>(vv) = *reinterpret_cast<const uint2*>(base + 2 * DIM);

    float q[4], k[4];
    {
        float2 t;
        t = __half22float2(qv[0]); q[0] = t.x; q[1] = t.y;
        t = __half22float2(qv[1]); q[2] = t.x; q[3] = t.y;
        t = __half22float2(kv[0]); k[0] = t.x; k[1] = t.y;
        t = __half22float2(kv[1]); k[2] = t.x; k[3] = t.y;
    }

    float sq = q[0] * q[0] + q[1] * q[1] + q[2] * q[2] + q[3] * q[3];
    float sk = k[0] * k[0] + k[1] * k[1] + k[2] * k[2] + k[3] * k[3];
#pragma unroll
    for (int o = 16; o; o >>= 1) {
        sq += __shfl_xor_sync(0xffffffffu, sq, o);
        sk += __shfl_xor_sync(0xffffffffu, sk, o);
    }
    const float rrq = rsqrtf(sq * (1.0f / HD) + 1e-6f);
    const float rrk = rsqrtf(sk * (1.0f / HD) + 1e-6f);

    float4 qsv = *reinterpret_cast<const float4*>(&qs[d0]);
    float4 ksv = *reinterpret_cast<const float4*>(&ks[d0]);
    float qn[4], kn[4];
    qn[0] = q[0] * rrq * qsv.x; qn[1] = q[1] * rrq * qsv.y;
    qn[2] = q[2] * rrq * qsv.z; qn[3] = q[3] * rrq * qsv.w;
    kn[0] = k[0] * rrk * ksv.x; kn[1] = k[1] * rrk * ksv.y;
    kn[2] = k[2] * rrk * ksv.z; kn[3] = k[3] * rrk * ksv.w;

    // RoPE: j = d0/2 and d0/2+1; pe row = 256 floats
    const float* pp = pe + (size_t)l * 256 + d0 * 2;
    float4 p0 = *reinterpret_cast<const float4*>(pp);      // j
    float4 p1 = *reinterpret_cast<const float4*>(pp + 4);  // j+1
    const float cs = SCALE * LOG2E;
    float qr[4], kr[4];
    qr[0] = (p0.x * qn[0] + p0.y * qn[1]) * cs;
    qr[1] = (p0.z * qn[0] + p0.w * qn[1]) * cs;
    qr[2] = (p1.x * qn[2] + p1.y * qn[3]) * cs;
    qr[3] = (p1.z * qn[2] + p1.w * qn[3]) * cs;
    kr[0] = p0.x * kn[0] + p0.y * kn[1];
    kr[1] = p0.z * kn[0] + p0.w * kn[1];
    kr[2] = p1.x * kn[2] + p1.y * kn[3];
    kr[3] = p1.z * kn[2] + p1.w * kn[3];

    const size_t idx = ((size_t)h * LEN + l) * HD + d0;
    *reinterpret_cast<uint2*>(&g_qh[idx]) =
        make_uint2(pack2h(qr[0], qr[1]), pack2h(qr[2], qr[3]));
    *reinterpret_cast<uint2*>(&g_kh[idx]) =
        make_uint2(pack2h(kr[0], kr[1]), pack2h(kr[2], kr[3]));

    const size_t vb = (size_t)h * HD * LEN + l;
    g_vth[vb + (size_t)(d0 + 0) * LEN] = vv[0].x;
    g_vth[vb + (size_t)(d0 + 1) * LEN] = vv[0].y;
    g_vth[vb + (size_t)(d0 + 2) * LEN] = vv[1].x;
    g_vth[vb + (size_t)(d0 + 3) * LEN] = vv[1].y;
}

// ---------------- launch ----------------
extern "C" void kernel_launch(void* const* d_in, const int* in_sizes, int n_in,
                              void* d_out, int out_size)
{
    const float* x      = (const float*)d_in[0];
    const float* pe     = (const float*)d_in[1];
    const float* w_qkv  = (const float*)d_in[2];
    const float* q_sc   = (const float*)d_in[3];
    const float* k_sc   = (const float*)d_in[4];
    const float* w_proj = (const float*)d_in[5];
    const float* b_proj = (const float*)d_in[6];
    float* out = (float*)d_out;

    __half *p_qkv, *p_xh, *p_wqh, *p_wph, *p_oh;
    cudaGetSymbolAddress((void**)&p_qkv, g_qkv);
    cudaGetSymbolAddress((void**)&p_xh,  g_xh);
    cudaGetSymbolAddress((void**)&p_wqh, g_wqh);
    cudaGetSymbolAddress((void**)&p_wph, g_wph);
    cudaGetSymbolAddress((void**)&p_oh,  g_oh);

    cudaFuncSetAttribute((const void*)gemm_nt_h2<__half>,
                         cudaFuncAttributeMaxDynamicSharedMemorySize, GSMEM);
    cudaFuncSetAttribute((const void*)gemm_nt_h2<float>,
                         cudaFuncAttributeMaxDynamicSharedMemorySize, GSMEM);
    cudaFuncSetAttribute((const void*)flash_attn,
                         cudaFuncAttributeMaxDynamicSharedMemorySize, FA_SMEM);

    // 0) round x, weights to fp16
    {
        const int total = SEG_X + SEG_WQ + SEG_WP;
        split_inputs<<<(total + 255) / 256, 256>>>(x, w_qkv, w_proj);
    }

    // 1) QKV = x @ w_qkv^T : [2048, 6144] fp16 output
    gemm_nt_h2<__half><<<dim3(6144 / 128, 2048 / 128, 1), 256, GSMEM>>>(
        p_xh, p_wqh, p_qkv, 2048, 2048, 2048, 6144, 1.0f, nullptr);

    // 2) QK RMSNorm + RoPE + V transpose (warp-per-head, shfl-only)
    qknorm_rope<<<LEN, 512>>>(pe, q_sc, k_sc);

    // 3) fused attention (f16x2 exp2, persistent Q, 3-stage K/V)
    flash_attn<<<dim3(LEN / 128, NH), 256, FA_SMEM>>>();

    // 4) out = O @ w_proj^T + b_proj : [2048, 2048] fp32
    gemm_nt_h2<float><<<dim3(2048 / 128, 2048 / 128, 1), 256, GSMEM>>>(
        p_oh, p_wph, out, 2048, 2048, 2048, 2048, 1.0f, b_proj);
}